// round 5
// baseline (speedup 1.0000x reference)
#include <cuda_runtime.h>

// Problem constants (fixed shapes)
#define E_EDGES    320000
#define N_ATOMS_C  20000
#define TRIP_CAP_C 4000000
#define D_MAX_C    64
#define NBLK       148
#define NTHR       512
#define ITEMS      5              // NTHR*ITEMS = 2560; 148*2560 = 378880 >= E
#define CHUNK      (NTHR * ITEMS)

// ---------------- scratch (device globals; no allocation allowed) ----------
__device__ int g_row[E_EDGES];               // source node if valid else -1
__device__ int g_deg[N_ATOMS_C];             // valid degree per node
__device__ int g_table[N_ATOMS_C * D_MAX_C]; // per-node edge slots (sorted in P2)
__device__ int g_bsum[NBLK];                 // per-block triplet-count partials
__device__ int g_bar_count;                  // barrier arrivals (returns to 0)
__device__ int g_bar_gen;                    // barrier generation (monotonic)

// ---------------- grid-wide barrier (all NBLK blocks resident) --------------
__device__ __forceinline__ void grid_sync() {
    __syncthreads();
    if (threadIdx.x == 0) {
        int gen = *(volatile int*)&g_bar_gen;
        __threadfence();                       // publish this block's writes
        int t = atomicAdd(&g_bar_count, 1);
        if (t == NBLK - 1) {
            atomicExch(&g_bar_count, 0);
            __threadfence();
            atomicAdd(&g_bar_gen, 1);          // release
        } else {
            while (*(volatile int*)&g_bar_gen == gen) { __nanosleep(64); }
        }
        __threadfence();                       // acquire
    }
    __syncthreads();
}

// ---------------- block-wide exclusive scan ---------------------------------
__device__ __forceinline__ int block_exscan(int v) {
    __shared__ int ws[32];
    int lane = threadIdx.x & 31, wid = threadIdx.x >> 5;
    int nw = NTHR >> 5;
    int x = v;
#pragma unroll
    for (int o = 1; o < 32; o <<= 1) {
        int y = __shfl_up_sync(0xffffffffu, x, o);
        if (lane >= o) x += y;
    }
    if (lane == 31) ws[wid] = x;
    __syncthreads();
    if (wid == 0) {
        int wv = (lane < nw) ? ws[lane] : 0;
        int wx = wv;
#pragma unroll
        for (int o = 1; o < 32; o <<= 1) {
            int y = __shfl_up_sync(0xffffffffu, wx, o);
            if (lane >= o) wx += y;
        }
        ws[lane] = wx - wv;
    }
    __syncthreads();
    int r = ws[wid] + x - v;
    __syncthreads();                           // ws reusable after return
    return r;
}

// ---------------- the whole pipeline in one persistent kernel ---------------
__global__ void __launch_bounds__(NTHR)
k_triplets(const float* __restrict__ vec, const int* __restrict__ ei_row,
           float* __restrict__ out) {
    const int t = threadIdx.x, b = blockIdx.x;
    const int gid = b * NTHR + t;
    const int GT = NBLK * NTHR;

    // P0: zero degrees
    for (int i = gid; i < N_ATOMS_C; i += GT) g_deg[i] = 0;
    grid_sync();  // B1

    // P1: classify + direct table scatter (slot = atomicAdd return)
    for (int e = gid; e < E_EDGES; e += GT) {
        float x = vec[3 * e + 0], y = vec[3 * e + 1], z = vec[3 * e + 2];
        float s = __fadd_rn(__fadd_rn(__fmul_rn(x, x), __fmul_rn(y, y)),
                            __fmul_rn(z, z));
        int r = -1;
        if (sqrtf(s) <= 1.5f) {
            int rr = ei_row[e];
            if (rr >= 0 && rr < N_ATOMS_C) {
                r = rr;
                int slot = atomicAdd(&g_deg[rr], 1);
                if (slot < D_MAX_C) g_table[rr * D_MAX_C + slot] = e;
            }
        }
        g_row[e] = r;
    }
    grid_sync();  // B2

    // P2a: per-block partial triplet counts over contiguous chunk
    const int base = b * CHUNK + t * ITEMS;
    int lsum = 0;
#pragma unroll
    for (int i = 0; i < ITEMS; i++) {
        int e = base + i;
        if (e < E_EDGES) {
            int r = g_row[e];
            if (r >= 0) lsum += min(g_deg[r], D_MAX_C) - 1;
        }
    }
    int tpre = block_exscan(lsum);              // thread prefix, kept in register
    if (t == NTHR - 1) g_bsum[b] = tpre + lsum;

    // P2b: per-node insertion sort (independent of P2a, same phase)
    for (int n = gid; n < N_ATOMS_C; n += GT) {
        int d = min(g_deg[n], D_MAX_C);
        int* rowp = &g_table[n * D_MAX_C];
        for (int i = 1; i < d; i++) {
            int key = rowp[i];
            int j = i - 1;
            while (j >= 0 && rowp[j] > key) { rowp[j + 1] = rowp[j]; j--; }
            rowp[j + 1] = key;
        }
    }
    grid_sync();  // B3

    // P3: every block redundantly scans the 148 partials (no extra barrier)
    __shared__ int s_boff, s_total;
    {
        int v = (t < NBLK) ? g_bsum[t] : 0;
        int ex = block_exscan(v);
        if (t == b) s_boff = ex;
        if (t == NBLK - 1) s_total = ex + v;
    }
    __syncthreads();

    // P4: emit triplets as float32
    {
        int off = s_boff + tpre;
        float* oj = out;
        float* ok = out + TRIP_CAP_C;
#pragma unroll
        for (int i = 0; i < ITEMS; i++) {
            int e = base + i;
            if (e >= E_EDGES) break;
            int r = g_row[e];
            if (r < 0) continue;
            int d = min(g_deg[r], D_MAX_C);
            const int* rowp = &g_table[r * D_MAX_C];
            float fe = (float)e;                 // < 2^24, exact
            for (int q = 0; q < d; q++) {
                int k = rowp[q];
                if (k != e) {
                    if (off >= 0 && off < TRIP_CAP_C) {
                        oj[off] = fe;
                        ok[off] = (float)k;
                    }
                    off++;
                }
            }
        }
    }

    // P5: fill dead tail [cnt, TRIP_CAP) of both halves with -1.0f.
    // Disjoint from emit's [0, cnt) => no barrier needed.
    {
        int cnt = s_total;
        if (cnt < 0) cnt = 0;
        if (cnt > TRIP_CAP_C) cnt = TRIP_CAP_C;
        int start4 = (cnt + 3) & ~3;
        if (start4 > TRIP_CAP_C) start4 = TRIP_CAP_C;
        float* oj = out;
        float* ok = out + TRIP_CAP_C;
        if (gid < start4 - cnt) {                // 0-3 head scalars per half
            oj[cnt + gid] = -1.0f;
            ok[cnt + gid] = -1.0f;
        }
        int n4 = (TRIP_CAP_C - start4) >> 2;     // TRIP_CAP_C % 4 == 0
        float4 vm = make_float4(-1.0f, -1.0f, -1.0f, -1.0f);
        float4* a = (float4*)(oj + start4);
        float4* c = (float4*)(ok + start4);
        for (int i = gid; i < n4; i += GT) {
            a[i] = vm;
            c[i] = vm;
        }
    }
}

// ---------------- launch -----------------------------------------------------
extern "C" void kernel_launch(void* const* d_in, const int* in_sizes, int n_in,
                              void* d_out, int out_size) {
    const float* vec    = (const float*)d_in[0];
    const int*   ei_row = (const int*)d_in[1];   // [2, E] int32; row = first E
    float* out = (float*)d_out;

    k_triplets<<<NBLK, NTHR>>>(vec, ei_row, out);
}